// round 16
// baseline (speedup 1.0000x reference)
#include <cuda_runtime.h>

#define H      4096
#define TMAX   16384
#define EXP    8
#define FULLM  0xFFFFFFFFu
#define STAGES 8
#define ROWB   16384            // bytes per full row
#define HROWB  8192             // bytes per half row (one block's share)

// fp32 logits accumulated by atomics: [row][expert] = 512 KB
__device__ float g_logits[(size_t)TMAX * EXP];
// per-row completion counters (16 contributing warps per row) = 64 KB
__device__ unsigned g_count[TMAX];

typedef unsigned long long u64;

__device__ __forceinline__ u64 fma2(u64 a, u64 b, u64 c) {
    u64 d; asm("fma.rn.f32x2 %0,%1,%2,%3;" : "=l"(d) : "l"(a), "l"(b), "l"(c)); return d;
}
__device__ __forceinline__ u64 mul2(u64 a, u64 b) {
    u64 d; asm("mul.rn.f32x2 %0,%1,%2;" : "=l"(d) : "l"(a), "l"(b)); return d;
}
__device__ __forceinline__ float hadd2(u64 v) {
    float lo = __uint_as_float((unsigned)v);
    float hi = __uint_as_float((unsigned)(v >> 32));
    return lo + hi;
}
__device__ __forceinline__ void lds128(u64& a, u64& b, unsigned addr) {
    asm volatile("ld.shared.v2.u64 {%0,%1},[%2];" : "=l"(a), "=l"(b) : "r"(addr));
}
__device__ __forceinline__ void cp16(unsigned saddr, const void* gaddr) {
    asm volatile("cp.async.cg.shared.global [%0], [%1], 16;" :: "r"(saddr), "l"(gaddr));
}
__device__ __forceinline__ void cp_commit() {
    asm volatile("cp.async.commit_group;" ::: "memory");
}
__device__ __forceinline__ void cp_waitN() {
    asm volatile("cp.async.wait_group %0;" :: "n"(STAGES - 1) : "memory");
}
// acq_rel gpu-scope fetch-add: release orders our prior logits atomics,
// acquire orders the finalizer's subsequent logits reads.
__device__ __forceinline__ unsigned atom_acqrel_add(unsigned* p) {
    unsigned old;
    asm volatile("atom.acq_rel.gpu.global.add.u32 %0, [%1], 1;"
                 : "=r"(old) : "l"(p) : "memory");
    return old;
}

// Reduce 8 per-lane values across 32 lanes (vector-halving butterfly, 9 shfls).
// Result: lane 4e holds the sum for expert e.
__device__ __forceinline__ float reduce8(float a[8]) {
    const int lane = threadIdx.x & 31;
    {
        bool hi = (lane & 16) != 0;
        float s0 = hi ? a[0] : a[4];
        float s1 = hi ? a[1] : a[5];
        float s2 = hi ? a[2] : a[6];
        float s3 = hi ? a[3] : a[7];
        s0 = __shfl_xor_sync(FULLM, s0, 16);
        s1 = __shfl_xor_sync(FULLM, s1, 16);
        s2 = __shfl_xor_sync(FULLM, s2, 16);
        s3 = __shfl_xor_sync(FULLM, s3, 16);
        a[0] = (hi ? a[4] : a[0]) + s0;
        a[1] = (hi ? a[5] : a[1]) + s1;
        a[2] = (hi ? a[6] : a[2]) + s2;
        a[3] = (hi ? a[7] : a[3]) + s3;
    }
    {
        bool hi = (lane & 8) != 0;
        float s0 = hi ? a[0] : a[2];
        float s1 = hi ? a[1] : a[3];
        s0 = __shfl_xor_sync(FULLM, s0, 8);
        s1 = __shfl_xor_sync(FULLM, s1, 8);
        a[0] = (hi ? a[2] : a[0]) + s0;
        a[1] = (hi ? a[3] : a[1]) + s1;
    }
    {
        bool hi = (lane & 4) != 0;
        float s0 = hi ? a[0] : a[1];
        s0 = __shfl_xor_sync(FULLM, s0, 4);
        a[0] = (hi ? a[1] : a[0]) + s0;
    }
    float v = a[0];
    v += __shfl_xor_sync(FULLM, v, 2);
    v += __shfl_xor_sync(FULLM, v, 1);
    return v;
}

// Finalize one row: read completed logits, softmax, top-2, write all outputs.
// Warp-uniform call; lanes 0..7 carry real data, shfl masks stay in-octet.
__device__ __forceinline__ void finalize_row(int row, int T, float* out, int flags) {
    const int lane = threadIdx.x & 31;
    float t = 0.0f;
    if (lane < 8) t = __ldcg(&g_logits[(size_t)row * EXP + lane]);

    float m = t;
    m = fmaxf(m, __shfl_xor_sync(FULLM, m, 4));
    m = fmaxf(m, __shfl_xor_sync(FULLM, m, 2));
    m = fmaxf(m, __shfl_xor_sync(FULLM, m, 1));
    float pz = __expf(t - m);
    float sden = pz;
    sden += __shfl_xor_sync(FULLM, sden, 4);
    sden += __shfl_xor_sync(FULLM, sden, 2);
    sden += __shfl_xor_sync(FULLM, sden, 1);
    float sc = __fdividef(pz, sden);   // lane e (<8): score of expert e

    float se[EXP];
#pragma unroll
    for (int j = 0; j < EXP; j++)
        se[j] = __shfl_sync(FULLM, sc, j);

    if (lane < 2) {
        float4 o = lane ? make_float4(se[4], se[5], se[6], se[7])
                        : make_float4(se[0], se[1], se[2], se[3]);
        reinterpret_cast<float4*>(out + (size_t)row * EXP)[lane] = o;
    }

    float w1 = se[0]; int i1 = 0;
#pragma unroll
    for (int j = 1; j < EXP; j++)
        if (se[j] > w1) { w1 = se[j]; i1 = j; }
    float w2 = -1.0f; int i2 = 0;
#pragma unroll
    for (int j = 0; j < EXP; j++)
        if (j != i1 && se[j] > w2) { w2 = se[j]; i2 = j; }

    if (lane == 2 && (flags & 1)) {
        float* outW = out + (size_t)T * EXP;
        outW[(size_t)row * 2 + 0] = w1;
        outW[(size_t)row * 2 + 1] = w2;
    }
    if (lane == 3 && (flags & 2)) {
        float* outI = out + (size_t)T * (EXP + 2);
        outI[(size_t)row * 2 + 0] = (float)i1;
        outI[(size_t)row * 2 + 1] = (float)i2;
    }
}

// ── Single fused kernel: streaming GEMV + self-finalizing rows.
//   2 blocks per SM; block (r0, half) owns half-row columns [half*2048,+2048).
//   256 threads; 8-deep per-thread cp.async pipeline. Warp partial -> 8
//   atomicAdds; lane 0 bumps the row's counter (acq_rel). The 16th arrival
//   finalizes the row — checked ONE row later so the atomic's return latency
//   hides behind the next row's streaming work.
__global__ void __launch_bounds__(256, 2)
router_fused(const float* __restrict__ x, const float* __restrict__ W, int T,
             float* __restrict__ out, int flags) {
    extern __shared__ char smem[];   // STAGES * 8KB = 64KB

    const int tid  = threadIdx.x;
    const int lane = tid & 31;
    const int half = blockIdx.x & 1;
    const int nb   = gridDim.x >> 1;
    const int r0   = blockIdx.x >> 1;

    const int colF = half * 2048;    // this block's first column (floats)

    // W regs: 8 experts x 2 chunks x 16B = 64 regs
    u64 wa0[EXP], wa1[EXP], wb0[EXP], wb1[EXP];
#pragma unroll
    for (int e = 0; e < EXP; e++) {
        ulonglong2 ta = *reinterpret_cast<const ulonglong2*>(W + e * H + colF + tid * 4);
        ulonglong2 tb = *reinterpret_cast<const ulonglong2*>(W + e * H + colF + 1024 + tid * 4);
        wa0[e] = ta.x; wa1[e] = ta.y;
        wb0[e] = tb.x; wb1[e] = tb.y;
    }

    unsigned sbase;
    asm("{ .reg .u64 t; cvta.to.shared.u64 t, %1; cvt.u32.u64 %0, t; }"
        : "=r"(sbase) : "l"(smem));
    const unsigned myA = sbase + tid * 16;   // chunk A slot
    const unsigned myB = myA + 4096;         // chunk B slot

    const char* xg = reinterpret_cast<const char*>(x);
    const size_t offA = (size_t)half * HROWB + tid * 16;
    const size_t offB = offA + 4096;

    // prologue: fill STAGES groups
#pragma unroll
    for (int s = 0; s < STAGES; s++) {
        int r = r0 + s * nb;
        if (r < T) {
            cp16(myA + s * HROWB, xg + (size_t)r * ROWB + offA);
            cp16(myB + s * HROWB, xg + (size_t)r * ROWB + offB);
        }
        cp_commit();
    }

    int s = 0;
    int pendR = -1;            // row whose counter return is in flight
    unsigned pendTok = 0;
    for (int r = r0; r < T; r += nb) {
        cp_waitN();
        __syncwarp();

        u64 ax0, ax1, bx0, bx1;
        lds128(ax0, ax1, myA + s * HROWB);
        lds128(bx0, bx1, myB + s * HROWB);

        // refill early so the LDGSTS stream never waits on the tail logic
        int rp = r + STAGES * nb;
        if (rp < T) {
            cp16(myA + s * HROWB, xg + (size_t)rp * ROWB + offA);
            cp16(myB + s * HROWB, xg + (size_t)rp * ROWB + offB);
        }
        cp_commit();
        s = (s == STAGES - 1) ? 0 : s + 1;

        float a8[EXP];
#pragma unroll
        for (int e = 0; e < EXP; e++) {
            u64 acc = mul2(ax0, wa0[e]);
            acc = fma2(ax1, wa1[e], acc);
            acc = fma2(bx0, wb0[e], acc);
            acc = fma2(bx1, wb1[e], acc);
            a8[e] = hadd2(acc);
        }

        float v = reduce8(a8);
        if ((lane & 3) == 0)
            atomicAdd(g_logits + (size_t)r * EXP + (lane >> 2), v);

        // counter bump for THIS row (release: orders the logits adds above)
        unsigned tok = 0;
        if (lane == 0) tok = atom_acqrel_add(&g_count[r]);

        // resolve the PREVIOUS row's pending token (latency now hidden)
        if (pendR >= 0) {
            unsigned t16 = __shfl_sync(FULLM, pendTok, 0);
            if (t16 == 15) finalize_row(pendR, T, out, flags);
        }
        pendR = r; pendTok = tok;
    }
    // drain the last pending row
    if (pendR >= 0) {
        unsigned t16 = __shfl_sync(FULLM, pendTok, 0);
        if (t16 == 15) finalize_row(pendR, T, out, flags);
    }
}

extern "C" void kernel_launch(void* const* d_in, const int* in_sizes, int n_in,
                              void* d_out, int out_size) {
    const float* x = (const float*)d_in[0];
    const float* W = (const float*)d_in[1];

    int T = in_sizes[0] / H;  // 16384

    int dev = 0;
    cudaGetDevice(&dev);
    int sm = 148;
    cudaDeviceGetAttribute(&sm, cudaDevAttrMultiProcessorCount, dev);

    int flags = 0;
    if (out_size >= T * (EXP + 2)) flags |= 1;
    if (out_size >= T * (EXP + 4)) flags |= 2;

    static void* logitsAddr = nullptr;
    static void* countAddr = nullptr;
    static int initDone = 0;
    if (!initDone) {
        cudaFuncSetAttribute(router_fused, cudaFuncAttributeMaxDynamicSharedMemorySize,
                             STAGES * HROWB);
        cudaGetSymbolAddress(&logitsAddr, g_logits);
        cudaGetSymbolAddress(&countAddr, g_count);
        initDone = 1;
    }

    // zero accumulators + counters (graph-capturable async memsets)
    cudaMemsetAsync(logitsAddr, 0, (size_t)T * EXP * sizeof(float), 0);
    cudaMemsetAsync(countAddr, 0, (size_t)T * sizeof(unsigned), 0);

    router_fused<<<2 * sm, 256, STAGES * HROWB>>>(x, W, T, (float*)d_out, flags);
}